// round 14
// baseline (speedup 1.0000x reference)
#include <cuda_runtime.h>
#include <cuda_fp16.h>
#include <cstdint>

#define NB  8
#define NPT 1024
#define DD  512
#define NH  8
#define DH  64
#define MM  (NB * NPT)
#define SCALE 0.04419417382415922f   // 1/sqrt(512)

// ---------------- scratch (device globals; allocation-free) ----------------
__device__ float  g_q  [(size_t)MM * DD];            // fp32 q (exact residual)
__device__ __half g_qh [(size_t)MM * DD];            // fp16 q
__device__ __half g_kh [(size_t)MM * DD];            // fp16 k
__device__ __half g_vh [(size_t)MM * DD];            // fp16 v
__device__ float  g_o  [(size_t)MM * DD];            // fp32 O (residual for out-proj)
__device__ __half g_oh [(size_t)MM * DD];            // fp16 O (mma operand)
__device__ __half g_Qin[(size_t)MM * DD];            // fp16 raw Q
__device__ __half g_Kin[(size_t)MM * DD];            // fp16 raw K
__device__ __half g_Wh [4][(size_t)DD * DD];         // fp16 Wq,Wk,Wv,Wo
__device__ __half g_A  [(size_t)NH * NB * NPT * NPT];// U = exp(s), fp16
__device__ float  g_Z  [(size_t)NH * NB * NPT];      // 1/rowsum

// ---------------- helpers ----------------
__device__ __forceinline__ void mma16h(float* c, uint32_t a0, uint32_t a1,
                                       uint32_t a2, uint32_t a3,
                                       uint32_t b0, uint32_t b1) {
    asm volatile(
        "mma.sync.aligned.m16n8k16.row.col.f32.f16.f16.f32 "
        "{%0,%1,%2,%3},{%4,%5,%6,%7},{%8,%9},{%0,%1,%2,%3};"
        : "+f"(c[0]), "+f"(c[1]), "+f"(c[2]), "+f"(c[3])
        : "r"(a0), "r"(a1), "r"(a2), "r"(a3), "r"(b0), "r"(b1));
}
__device__ __forceinline__ void ldmx4(uint32_t& a0, uint32_t& a1, uint32_t& a2,
                                      uint32_t& a3, uint32_t addr) {
    asm volatile("ldmatrix.sync.aligned.m8n8.x4.shared.b16 {%0,%1,%2,%3}, [%4];"
                 : "=r"(a0), "=r"(a1), "=r"(a2), "=r"(a3) : "r"(addr));
}
__device__ __forceinline__ void ldmx2(uint32_t& b0, uint32_t& b1, uint32_t addr) {
    asm volatile("ldmatrix.sync.aligned.m8n8.x2.shared.b16 {%0,%1}, [%2];"
                 : "=r"(b0), "=r"(b1) : "r"(addr));
}
__device__ __forceinline__ void ldmx2t(uint32_t& b0, uint32_t& b1, uint32_t addr) {
    asm volatile("ldmatrix.sync.aligned.m8n8.x2.trans.shared.b16 {%0,%1}, [%2];"
                 : "=r"(b0), "=r"(b1) : "r"(addr));
}
__device__ __forceinline__ void cpa16(uint32_t dst, const void* src) {
    asm volatile("cp.async.cg.shared.global [%0], [%1], 16;" :: "r"(dst), "l"(src));
}
#define CP_COMMIT() asm volatile("cp.async.commit_group;")
#define CP_WAIT(N)  asm volatile("cp.async.wait_group %0;" :: "n"(N))

// ======================================================================
// fp32 -> fp16 conversion, single launch.
// ======================================================================
__global__ void __launch_bounds__(256) cvt_all(
    const float* __restrict__ Q, const float* __restrict__ K,
    const float* __restrict__ W0, const float* __restrict__ W1,
    const float* __restrict__ W2, const float* __restrict__ W3)
{
    const int job = blockIdx.y;
    if (job >= 2) {
        if (blockIdx.x >= 64) return;
        const float* ws[4] = {W0, W1, W2, W3};
        const float4* src = (const float4*)ws[job - 2];
        __half2* dst = (__half2*)g_Wh[job - 2];
        int i = blockIdx.x * 256 + threadIdx.x;
#pragma unroll
        for (int t = 0; t < 4; t++) {
            int idx = i + t * (64 * 256);
            float4 v = src[idx];
            dst[2 * idx]     = __floats2half2_rn(v.x, v.y);
            dst[2 * idx + 1] = __floats2half2_rn(v.z, v.w);
        }
        return;
    }
    const float4* src = (const float4*)(job ? K : Q);
    __half2* dst = (__half2*)(job ? g_Kin : g_Qin);
    int i = blockIdx.x * 256 + threadIdx.x;
#pragma unroll
    for (int t = 0; t < 4; t++) {
        int idx = i + t * (1024 * 256);
        float4 v = src[idx];
        dst[2 * idx]     = __floats2half2_rn(v.x, v.y);
        dst[2 * idx + 1] = __floats2half2_rn(v.z, v.w);
    }
}

// ======================================================================
// GEMM core 64x64, 3-stage cp.async pipeline, K-chunk 64. (R12, proven)
// smem bytes: Xs[3] 64x144B | Ws[3] 64x144B = 55296
// ======================================================================
#define GX_B(bu) ((bu) * 9216)
#define GW_B(bu) (27648 + (bu) * 9216)
#define GEMM_SMEM_BYTES 55296

struct GemmAcc { float a[2][4][4]; };

__device__ __forceinline__ void gemm_stage_load(
    const __half* __restrict__ Xh, const __half* __restrict__ Wh,
    uint32_t sbase, int m0, int n0, int tid, int stage, int k0)
{
#pragma unroll
    for (int t = 0; t < 4; t++) {
        int c = tid + (t << 7);
        int rr = c >> 3, seg = c & 7;
        cpa16(sbase + GX_B(stage) + rr * 144 + seg * 16,
              (const char*)(Xh + (size_t)(m0 + rr) * DD + k0) + seg * 16);
        cpa16(sbase + GW_B(stage) + rr * 144 + seg * 16,
              (const char*)(Wh + (size_t)(k0 + rr) * DD + n0) + seg * 16);
    }
    CP_COMMIT();
}

__device__ __forceinline__ void gemm_core64(
    const __half* __restrict__ Xh, const __half* __restrict__ Wh,
    uint32_t sbase, int m0, int n0, int wm, int wn,
    int tid, int lane, GemmAcc& A)
{
#pragma unroll
    for (int mf = 0; mf < 2; mf++)
#pragma unroll
        for (int nf = 0; nf < 4; nf++)
#pragma unroll
            for (int x = 0; x < 4; x++) A.a[mf][nf][x] = 0.f;

    gemm_stage_load(Xh, Wh, sbase, m0, n0, tid, 0, 0);
    gemm_stage_load(Xh, Wh, sbase, m0, n0, tid, 1, 64);

    const uint32_t arow = (uint32_t)((lane & 7) + (((lane >> 3) & 1) << 3));
    const uint32_t akoff = ((lane >> 4) & 1) << 4;
    const uint32_t brow = (uint32_t)(lane & 15);

    int buf = 0;
    for (int kc64 = 0; kc64 < 8; kc64++) {
        if (kc64 < 7) { CP_WAIT(1); } else { CP_WAIT(0); }
        __syncthreads();

        const uint32_t xsb = sbase + GX_B(buf);
        const uint32_t wsb = sbase + GW_B(buf);

        if (kc64 + 2 < 8) {
            int nb = buf + 2; if (nb >= 3) nb -= 3;
            gemm_stage_load(Xh, Wh, sbase, m0, n0, tid, nb, (kc64 + 2) << 6);
        }

#pragma unroll
        for (int kc = 0; kc < 4; kc++) {
            uint32_t af[2][4];
#pragma unroll
            for (int mf = 0; mf < 2; mf++)
                ldmx4(af[mf][0], af[mf][1], af[mf][2], af[mf][3],
                      xsb + (uint32_t)(wm + (mf << 4) + arow) * 144 + akoff + kc * 32);
#pragma unroll
            for (int nf = 0; nf < 4; nf++) {
                uint32_t b0, b1;
                ldmx2t(b0, b1, wsb + ((kc << 4) + brow) * 144 + wn * 2 + (nf << 4));
#pragma unroll
                for (int mf = 0; mf < 2; mf++)
                    mma16h(A.a[mf][nf], af[mf][0], af[mf][1], af[mf][2], af[mf][3], b0, b1);
            }
        }
        if (++buf >= 3) buf = 0;
    }
}

extern __shared__ uint32_t gsm[];

// ---- merged projection GEMM: grid (8, 128, 3); z: 0=q, 1=k, 2=v ----
__global__ void __launch_bounds__(128, 4) proj3(
    const float* __restrict__ bq, const float* __restrict__ bk,
    const float* __restrict__ bv)
{
    const uint32_t sbase = (uint32_t)__cvta_generic_to_shared(gsm);
    const int tid = threadIdx.x, lane = tid & 31, w = tid >> 5;
    const int m0 = blockIdx.y << 6, n0 = blockIdx.x << 6;
    const int wm = (w & 1) << 5, wn = (w >> 1) << 5;
    const int z = blockIdx.z;

    const __half* Xh = (z == 0) ? g_Qin : g_Kin;
    const __half* Wh = g_Wh[z];
    const float* bias = (z == 0) ? bq : (z == 1) ? bk : bv;

    GemmAcc A;
    gemm_core64(Xh, Wh, sbase, m0, n0, wm, wn, tid, lane, A);

    __half2* Ch = (__half2*)((z == 0) ? g_qh : (z == 1) ? g_kh : g_vh);
#pragma unroll
    for (int mf = 0; mf < 2; mf++) {
        int row = m0 + wm + (mf << 4) + (lane >> 2);
#pragma unroll
        for (int nf = 0; nf < 4; nf++) {
            int col = n0 + wn + (nf << 3) + ((lane & 3) << 1);
            float2 bb = *(const float2*)(bias + col);
            float2 v0 = make_float2(A.a[mf][nf][0] + bb.x, A.a[mf][nf][1] + bb.y);
            float2 v1 = make_float2(A.a[mf][nf][2] + bb.x, A.a[mf][nf][3] + bb.y);
            Ch[(size_t)row * (DD / 2) + (col >> 1)]       = __floats2half2_rn(v0.x, v0.y);
            Ch[(size_t)(row + 8) * (DD / 2) + (col >> 1)] = __floats2half2_rn(v1.x, v1.y);
            if (z == 0) {
                *(float2*)(g_q + (size_t)row * DD + col) = v0;
                *(float2*)(g_q + (size_t)(row + 8) * DD + col) = v1;
            }
        }
    }
}

// ---- out-projection: C = R + relu(O@Wo + bo), grid (8, 128) ----
__global__ void __launch_bounds__(128, 4) outproj(
    const float* __restrict__ bo, float* __restrict__ C)
{
    const uint32_t sbase = (uint32_t)__cvta_generic_to_shared(gsm);
    const int tid = threadIdx.x, lane = tid & 31, w = tid >> 5;
    const int m0 = blockIdx.y << 6, n0 = blockIdx.x << 6;
    const int wm = (w & 1) << 5, wn = (w >> 1) << 5;

    GemmAcc A;
    gemm_core64(g_oh, g_Wh[3], sbase, m0, n0, wm, wn, tid, lane, A);

#pragma unroll
    for (int mf = 0; mf < 2; mf++) {
        int row = m0 + wm + (mf << 4) + (lane >> 2);
#pragma unroll
        for (int nf = 0; nf < 4; nf++) {
            int col = n0 + wn + (nf << 3) + ((lane & 3) << 1);
            float2 bb = *(const float2*)(bo + col);
            float2 v0 = make_float2(A.a[mf][nf][0] + bb.x, A.a[mf][nf][1] + bb.y);
            float2 v1 = make_float2(A.a[mf][nf][2] + bb.x, A.a[mf][nf][3] + bb.y);
            float2 r0 = *(const float2*)(g_o + (size_t)row * DD + col);
            float2 r1 = *(const float2*)(g_o + (size_t)(row + 8) * DD + col);
            v0.x = r0.x + fmaxf(v0.x, 0.f); v0.y = r0.y + fmaxf(v0.y, 0.f);
            v1.x = r1.x + fmaxf(v1.x, 0.f); v1.y = r1.y + fmaxf(v1.y, 0.f);
            *(float2*)(C + (size_t)row * DD + col) = v0;
            *(float2*)(C + (size_t)(row + 8) * DD + col) = v1;
        }
    }
}

// ======================================================================
// Fused attention v5: smem compacted — K buffer 1 reuses the Q region
// after the Q-fragment hoist (safe: hoist reads complete before the
// first in-loop __syncthreads that precedes the overwrite).
// 4 warps x 16 i-rows, grid (16, 64), 128 threads, 5 CTAs/SM.
// smem: [0,9216) Qs then K1 | [9216,18432) K0 | [18432,27648) V0
//       | [27648,36864) V1  = 36864 B
// ======================================================================
#define QS_B 0
#define KS_B(bu) ((bu) ? 0 : 9216)
#define VS_B(bu) (18432 + (bu) * 9216)
#define FUSED_SMEM_BYTES 36864

extern __shared__ uint32_t smw[];

__global__ void __launch_bounds__(128, 5) fused_attn()
{
    const uint32_t sbase = (uint32_t)__cvta_generic_to_shared(smw);

    const int tid = threadIdx.x, lane = tid & 31, wid = tid >> 5;
    const int hb = blockIdx.y, h = hb >> 3, b = hb & 7;
    const int i0 = blockIdx.x << 6;
    const int r = (wid << 4) + (lane >> 2);

    {
        const __half* src = g_qh + (size_t)(b * NPT + i0) * DD + h * DH;
#pragma unroll
        for (int t = 0; t < 4; t++) {
            int c = tid + (t << 7);
            int rr = c >> 3, seg = c & 7;
            cpa16(sbase + QS_B + rr * 144 + seg * 16,
                  (const char*)(src + (size_t)rr * DD) + seg * 16);
        }
        CP_COMMIT();
    }
    const __half* kbase = g_kh + (size_t)(b * NPT) * DD + h * DH;
    const __half* vbase = g_vh + (size_t)(b * NPT) * DD + h * DH;
#pragma unroll
    for (int t = 0; t < 4; t++) {
        int c = tid + (t << 7);
        int rr = c >> 3, seg = c & 7;
        cpa16(sbase + KS_B(0) + rr * 144 + seg * 16,
              (const char*)(kbase + (size_t)rr * DD) + seg * 16);
        cpa16(sbase + VS_B(0) + rr * 144 + seg * 16,
              (const char*)(vbase + (size_t)rr * DD) + seg * 16);
    }
    CP_COMMIT();

    uint32_t qf[4][4];
    CP_WAIT(1);
    __syncthreads();
    {
        const uint32_t qrow = (uint32_t)((wid << 4) + (lane & 7) + (((lane >> 3) & 1) << 3));
        const uint32_t koff = ((lane >> 4) & 1) << 4;
#pragma unroll
        for (int kc = 0; kc < 4; kc++)
            ldmx4(qf[kc][0], qf[kc][1], qf[kc][2], qf[kc][3],
                  sbase + QS_B + qrow * 144 + koff + kc * 32);
    }

    float oacc[8][4];
#pragma unroll
    for (int nf = 0; nf < 8; nf++)
#pragma unroll
        for (int x = 0; x < 4; x++) oacc[nf][x] = 0.f;
    float zl0 = 0.f, zl1 = 0.f;

    __half2* Aout = (__half2*)(g_A + (size_t)hb * NPT * NPT);

    for (int it = 0; it < 16; it++) {
        const int cur = it & 1;
        const uint32_t ksb = sbase + KS_B(cur);
        const uint32_t vsb = sbase + VS_B(cur);
        const int j0 = it << 6;

        CP_WAIT(0);
        __syncthreads();   // all warps past Q-hoist/prev-iter reads before overwrite

        if (it + 1 < 16) {
            const int nb = cur ^ 1;
            const __half* kc = kbase + (size_t)(j0 + 64) * DD;
            const __half* vc = vbase + (size_t)(j0 + 64) * DD;
#pragma unroll
            for (int t = 0; t < 4; t++) {
                int c = tid + (t << 7);
                int rr = c >> 3, seg = c & 7;
                cpa16(sbase + KS_B(nb) + rr * 144 + seg * 16,
                      (const char*)(kc + (size_t)rr * DD) + seg * 16);
                cpa16(sbase + VS_B(nb) + rr * 144 + seg * 16,
                      (const char*)(vc + (size_t)rr * DD) + seg * 16);
            }
            CP_COMMIT();
        }

        const uint32_t kboff = (((lane >> 3) & 1) << 4);
#pragma unroll
        for (int ks = 0; ks < 4; ks++) {
            uint32_t pe0, pe1, po0, po1;
#pragma unroll
            for (int t = 0; t < 2; t++) {
                const int nf = (ks << 1) + t;
                float s4[4] = {0.f, 0.f, 0.f, 0.f};
                uint32_t baddr = ksb + (uint32_t)((nf << 3) + (lane & 7)) * 144 + kboff;
#pragma unroll
                for (int kc = 0; kc < 4; kc++) {
                    uint32_t b0, b1;
                    ldmx2(b0, b1, baddr + kc * 32);
                    mma16h(s4, qf[kc][0], qf[kc][1], qf[kc][2], qf[kc][3], b0, b1);
                }
                float p0 = __expf(s4[0] * SCALE);
                float p1 = __expf(s4[1] * SCALE);
                float p2 = __expf(s4[2] * SCALE);
                float p3 = __expf(s4[3] * SCALE);
                zl0 += p0 + p1;
                zl1 += p2 + p3;
                __half2 lo = __floats2half2_rn(p0, p1);
                __half2 hi = __floats2half2_rn(p2, p3);
                int col = j0 + (nf << 3) + ((lane & 3) << 1);
                Aout[(size_t)(i0 + r) * (NPT >> 1) + (col >> 1)]     = lo;
                Aout[(size_t)(i0 + r + 8) * (NPT >> 1) + (col >> 1)] = hi;
                if (t == 0) { pe0 = *(uint32_t*)&lo; pe1 = *(uint32_t*)&hi; }
                else        { po0 = *(uint32_t*)&lo; po1 = *(uint32_t*)&hi; }
            }
            uint32_t rowaddr = vsb + (uint32_t)((ks << 4) + (lane & 15)) * 144;
#pragma unroll
            for (int nf2 = 0; nf2 < 8; nf2++) {
                uint32_t b0, b1;
                ldmx2t(b0, b1, rowaddr + (nf2 << 4));
                mma16h(oacc[nf2], pe0, pe1, po0, po1, b0, b1);
            }
        }
    }

    zl0 += __shfl_xor_sync(0xffffffffu, zl0, 1);
    zl0 += __shfl_xor_sync(0xffffffffu, zl0, 2);
    zl1 += __shfl_xor_sync(0xffffffffu, zl1, 1);
    zl1 += __shfl_xor_sync(0xffffffffu, zl1, 2);
    float iz0 = 1.0f / zl0, iz1 = 1.0f / zl1;
    if ((lane & 3) == 0) {
        g_Z[(size_t)hb * NPT + i0 + r]     = iz0;
        g_Z[(size_t)hb * NPT + i0 + r + 8] = iz1;
    }

    __half2* Oh = (__half2*)g_oh;
#pragma unroll
    for (int nf = 0; nf < 8; nf++) {
        int d = (nf << 3) + ((lane & 3) << 1);
        size_t gi0 = (size_t)(b * NPT + i0 + r) * DD + h * DH + d;
        size_t gi1 = gi0 + (size_t)8 * DD;
        float2 q0 = *(const float2*)(g_q + gi0);
        float2 q1 = *(const float2*)(g_q + gi1);
        float2 o0 = make_float2(q0.x + oacc[nf][0] * iz0, q0.y + oacc[nf][1] * iz0);
        float2 o1 = make_float2(q1.x + oacc[nf][2] * iz1, q1.y + oacc[nf][3] * iz1);
        *(float2*)(g_o + gi0) = o0;
        *(float2*)(g_o + gi1) = o1;
        Oh[gi0 >> 1] = __floats2half2_rn(o0.x, o0.y);
        Oh[gi1 >> 1] = __floats2half2_rn(o1.x, o1.y);
    }
}

// ======================================================================
// Am[b, j, i] = (1/8) * sum_h U[h,b,i,j] * invZ[h,b,i]   (half2 reads)
// ======================================================================
__global__ void __launch_bounds__(256) meanA_kernel(float* __restrict__ out)
{
    __shared__ float s[64][33];
    __shared__ float ziv[8][32];
    const int b  = blockIdx.z;
    const int i0 = blockIdx.x << 5;
    const int j0 = blockIdx.y << 6;
    const int tx = threadIdx.x & 31;
    const int ty = threadIdx.x >> 5;

    ziv[ty][tx] = g_Z[(size_t)(ty * NB + b) * NPT + i0 + tx];
    __syncthreads();

    float2 acc[4];
#pragma unroll
    for (int r = 0; r < 4; r++) acc[r] = make_float2(0.f, 0.f);

#pragma unroll
    for (int h = 0; h < 8; h++) {
        const __half2* base = (const __half2*)(
            g_A + ((size_t)(h * NB + b) * NPT + i0) * NPT + j0);
#pragma unroll
        for (int r = 0; r < 4; r++) {
            int ii = ty + (r << 3);
            float2 f = __half22float2(base[(size_t)ii * (NPT >> 1) + tx]);
            float z = ziv[h][ii];
            acc[r].x += f.x * z;
            acc[r].y += f.y * z;
        }
    }
#pragma unroll
    for (int r = 0; r < 4; r++) {
        int ii = ty + (r << 3);
        s[2 * tx][ii]     = acc[r].x * 0.125f;
        s[2 * tx + 1][ii] = acc[r].y * 0.125f;
    }
    __syncthreads();

    float* ob = out + ((size_t)b * NPT + j0) * NPT + i0;
#pragma unroll
    for (int rr = 0; rr < 8; rr++) {
        int jj = ty + (rr << 3);
        ob[(size_t)jj * NPT + tx] = s[jj][tx];
    }
}

// ======================================================================
// Launch — meanA forked onto a side stream, overlapping outproj.
// ======================================================================
extern "C" void kernel_launch(void* const* d_in, const int* in_sizes, int n_in,
                              void* d_out, int out_size)
{
    const float* Q  = (const float*)d_in[0];
    const float* K  = (const float*)d_in[1];
    const float* Wq = (const float*)d_in[2];
    const float* bq = (const float*)d_in[3];
    const float* Wk = (const float*)d_in[4];
    const float* bk = (const float*)d_in[5];
    const float* Wv = (const float*)d_in[6];
    const float* bv = (const float*)d_in[7];
    const float* Wo = (const float*)d_in[8];
    const float* bo = (const float*)d_in[9];
    float* out = (float*)d_out;

    static bool init = false;
    static cudaStream_t s2;
    static cudaEvent_t evFork, evJoin;
    if (!init) {
        cudaFuncSetAttribute(fused_attn, cudaFuncAttributeMaxDynamicSharedMemorySize,
                             FUSED_SMEM_BYTES);
        cudaFuncSetAttribute(proj3, cudaFuncAttributeMaxDynamicSharedMemorySize,
                             GEMM_SMEM_BYTES);
        cudaFuncSetAttribute(outproj, cudaFuncAttributeMaxDynamicSharedMemorySize,
                             GEMM_SMEM_BYTES);
        cudaStreamCreateWithFlags(&s2, cudaStreamNonBlocking);
        cudaEventCreateWithFlags(&evFork, cudaEventDisableTiming);
        cudaEventCreateWithFlags(&evJoin, cudaEventDisableTiming);
        init = true;
    }

    cvt_all<<<dim3(1024, 6), 256>>>(Q, K, Wq, Wk, Wv, Wo);

    proj3<<<dim3(8, 128, 3), 128, GEMM_SMEM_BYTES>>>(bq, bk, bv);

    fused_attn<<<dim3(16, 64), 128, FUSED_SMEM_BYTES>>>();

    // fork: meanA (reads g_A, g_Z) runs concurrently with outproj (reads g_oh, g_o)
    cudaEventRecord(evFork, 0);
    cudaStreamWaitEvent(s2, evFork, 0);
    meanA_kernel<<<dim3(32, 16, 8), 256, 0, s2>>>(out + (size_t)MM * DD);

    outproj<<<dim3(8, 128), 128, GEMM_SMEM_BYTES>>>(bo, out);

    // join
    cudaEventRecord(evJoin, s2);
    cudaStreamWaitEvent(0, evJoin, 0);
}

// round 15
// speedup vs baseline: 1.0743x; 1.0743x over previous
#include <cuda_runtime.h>
#include <cuda_fp16.h>
#include <cstdint>

#define NB  8
#define NPT 1024
#define DD  512
#define NH  8
#define DH  64
#define MM  (NB * NPT)
#define SCALE 0.04419417382415922f                 // 1/sqrt(512)
#define SCLOG2E (0.04419417382415922f * 1.4426950408889634f)

// ---------------- scratch (device globals; allocation-free) ----------------
__device__ float  g_q  [(size_t)MM * DD];            // fp32 q (exact residual)
__device__ __half g_qh [(size_t)MM * DD];            // fp16 q
__device__ __half g_kh [(size_t)MM * DD];            // fp16 k
__device__ __half g_vh [(size_t)MM * DD];            // fp16 v
__device__ float  g_o  [(size_t)MM * DD];            // fp32 O (residual for out-proj)
__device__ __half g_oh [(size_t)MM * DD];            // fp16 O (mma operand)
__device__ __half g_Qin[(size_t)MM * DD];            // fp16 raw Q
__device__ __half g_Kin[(size_t)MM * DD];            // fp16 raw K
__device__ __half g_Wh [4][(size_t)DD * DD];         // fp16 Wq,Wk,Wv,Wo
__device__ __half g_A  [(size_t)NH * NB * NPT * NPT];// U = exp(s), fp16
__device__ float  g_Z  [(size_t)NH * NB * NPT];      // 1/rowsum

// ---------------- helpers ----------------
__device__ __forceinline__ void mma16h(float* c, uint32_t a0, uint32_t a1,
                                       uint32_t a2, uint32_t a3,
                                       uint32_t b0, uint32_t b1) {
    asm volatile(
        "mma.sync.aligned.m16n8k16.row.col.f32.f16.f16.f32 "
        "{%0,%1,%2,%3},{%4,%5,%6,%7},{%8,%9},{%0,%1,%2,%3};"
        : "+f"(c[0]), "+f"(c[1]), "+f"(c[2]), "+f"(c[3])
        : "r"(a0), "r"(a1), "r"(a2), "r"(a3), "r"(b0), "r"(b1));
}
__device__ __forceinline__ void ldmx4(uint32_t& a0, uint32_t& a1, uint32_t& a2,
                                      uint32_t& a3, uint32_t addr) {
    asm volatile("ldmatrix.sync.aligned.m8n8.x4.shared.b16 {%0,%1,%2,%3}, [%4];"
                 : "=r"(a0), "=r"(a1), "=r"(a2), "=r"(a3) : "r"(addr));
}
__device__ __forceinline__ void ldmx2(uint32_t& b0, uint32_t& b1, uint32_t addr) {
    asm volatile("ldmatrix.sync.aligned.m8n8.x2.shared.b16 {%0,%1}, [%2];"
                 : "=r"(b0), "=r"(b1) : "r"(addr));
}
__device__ __forceinline__ void ldmx2t(uint32_t& b0, uint32_t& b1, uint32_t addr) {
    asm volatile("ldmatrix.sync.aligned.m8n8.x2.trans.shared.b16 {%0,%1}, [%2];"
                 : "=r"(b0), "=r"(b1) : "r"(addr));
}
__device__ __forceinline__ void cpa16(uint32_t dst, const void* src) {
    asm volatile("cp.async.cg.shared.global [%0], [%1], 16;" :: "r"(dst), "l"(src));
}
#define CP_COMMIT() asm volatile("cp.async.commit_group;")
#define CP_WAIT(N)  asm volatile("cp.async.wait_group %0;" :: "n"(N))

// ======================================================================
// fp32 -> fp16 conversion, single launch.
// ======================================================================
__global__ void __launch_bounds__(256) cvt_all(
    const float* __restrict__ Q, const float* __restrict__ K,
    const float* __restrict__ W0, const float* __restrict__ W1,
    const float* __restrict__ W2, const float* __restrict__ W3)
{
    const int job = blockIdx.y;
    if (job >= 2) {
        if (blockIdx.x >= 64) return;
        const float* ws[4] = {W0, W1, W2, W3};
        const float4* src = (const float4*)ws[job - 2];
        __half2* dst = (__half2*)g_Wh[job - 2];
        int i = blockIdx.x * 256 + threadIdx.x;
#pragma unroll
        for (int t = 0; t < 4; t++) {
            int idx = i + t * (64 * 256);
            float4 v = src[idx];
            dst[2 * idx]     = __floats2half2_rn(v.x, v.y);
            dst[2 * idx + 1] = __floats2half2_rn(v.z, v.w);
        }
        return;
    }
    const float4* src = (const float4*)(job ? K : Q);
    __half2* dst = (__half2*)(job ? g_Kin : g_Qin);
    int i = blockIdx.x * 256 + threadIdx.x;
#pragma unroll
    for (int t = 0; t < 4; t++) {
        int idx = i + t * (1024 * 256);
        float4 v = src[idx];
        dst[2 * idx]     = __floats2half2_rn(v.x, v.y);
        dst[2 * idx + 1] = __floats2half2_rn(v.z, v.w);
    }
}

// ======================================================================
// GEMM core 64x64, 3-stage cp.async pipeline, K-chunk 64. (R12, proven)
// smem bytes: Xs[3] 64x144B | Ws[3] 64x144B = 55296
// ======================================================================
#define GX_B(bu) ((bu) * 9216)
#define GW_B(bu) (27648 + (bu) * 9216)
#define GEMM_SMEM_BYTES 55296

struct GemmAcc { float a[2][4][4]; };

__device__ __forceinline__ void gemm_stage_load(
    const __half* __restrict__ Xh, const __half* __restrict__ Wh,
    uint32_t sbase, int m0, int n0, int tid, int stage, int k0)
{
#pragma unroll
    for (int t = 0; t < 4; t++) {
        int c = tid + (t << 7);
        int rr = c >> 3, seg = c & 7;
        cpa16(sbase + GX_B(stage) + rr * 144 + seg * 16,
              (const char*)(Xh + (size_t)(m0 + rr) * DD + k0) + seg * 16);
        cpa16(sbase + GW_B(stage) + rr * 144 + seg * 16,
              (const char*)(Wh + (size_t)(k0 + rr) * DD + n0) + seg * 16);
    }
    CP_COMMIT();
}

__device__ __forceinline__ void gemm_core64(
    const __half* __restrict__ Xh, const __half* __restrict__ Wh,
    uint32_t sbase, int m0, int n0, int wm, int wn,
    int tid, int lane, GemmAcc& A)
{
#pragma unroll
    for (int mf = 0; mf < 2; mf++)
#pragma unroll
        for (int nf = 0; nf < 4; nf++)
#pragma unroll
            for (int x = 0; x < 4; x++) A.a[mf][nf][x] = 0.f;

    gemm_stage_load(Xh, Wh, sbase, m0, n0, tid, 0, 0);
    gemm_stage_load(Xh, Wh, sbase, m0, n0, tid, 1, 64);

    const uint32_t arow = (uint32_t)((lane & 7) + (((lane >> 3) & 1) << 3));
    const uint32_t akoff = ((lane >> 4) & 1) << 4;
    const uint32_t brow = (uint32_t)(lane & 15);

    int buf = 0;
    for (int kc64 = 0; kc64 < 8; kc64++) {
        if (kc64 < 7) { CP_WAIT(1); } else { CP_WAIT(0); }
        __syncthreads();

        const uint32_t xsb = sbase + GX_B(buf);
        const uint32_t wsb = sbase + GW_B(buf);

        if (kc64 + 2 < 8) {
            int nb = buf + 2; if (nb >= 3) nb -= 3;
            gemm_stage_load(Xh, Wh, sbase, m0, n0, tid, nb, (kc64 + 2) << 6);
        }

#pragma unroll
        for (int kc = 0; kc < 4; kc++) {
            uint32_t af[2][4];
#pragma unroll
            for (int mf = 0; mf < 2; mf++)
                ldmx4(af[mf][0], af[mf][1], af[mf][2], af[mf][3],
                      xsb + (uint32_t)(wm + (mf << 4) + arow) * 144 + akoff + kc * 32);
#pragma unroll
            for (int nf = 0; nf < 4; nf++) {
                uint32_t b0, b1;
                ldmx2t(b0, b1, wsb + ((kc << 4) + brow) * 144 + wn * 2 + (nf << 4));
#pragma unroll
                for (int mf = 0; mf < 2; mf++)
                    mma16h(A.a[mf][nf], af[mf][0], af[mf][1], af[mf][2], af[mf][3], b0, b1);
            }
        }
        if (++buf >= 3) buf = 0;
    }
}

extern __shared__ uint32_t gsm[];

// ---- merged projection GEMM: grid (8, 128, 3); z: 0=q, 1=k, 2=v ----
__global__ void __launch_bounds__(128, 4) proj3(
    const float* __restrict__ bq, const float* __restrict__ bk,
    const float* __restrict__ bv)
{
    const uint32_t sbase = (uint32_t)__cvta_generic_to_shared(gsm);
    const int tid = threadIdx.x, lane = tid & 31, w = tid >> 5;
    const int m0 = blockIdx.y << 6, n0 = blockIdx.x << 6;
    const int wm = (w & 1) << 5, wn = (w >> 1) << 5;
    const int z = blockIdx.z;

    const __half* Xh = (z == 0) ? g_Qin : g_Kin;
    const __half* Wh = g_Wh[z];
    const float* bias = (z == 0) ? bq : (z == 1) ? bk : bv;

    GemmAcc A;
    gemm_core64(Xh, Wh, sbase, m0, n0, wm, wn, tid, lane, A);

    __half2* Ch = (__half2*)((z == 0) ? g_qh : (z == 1) ? g_kh : g_vh);
#pragma unroll
    for (int mf = 0; mf < 2; mf++) {
        int row = m0 + wm + (mf << 4) + (lane >> 2);
#pragma unroll
        for (int nf = 0; nf < 4; nf++) {
            int col = n0 + wn + (nf << 3) + ((lane & 3) << 1);
            float2 bb = *(const float2*)(bias + col);
            float2 v0 = make_float2(A.a[mf][nf][0] + bb.x, A.a[mf][nf][1] + bb.y);
            float2 v1 = make_float2(A.a[mf][nf][2] + bb.x, A.a[mf][nf][3] + bb.y);
            Ch[(size_t)row * (DD / 2) + (col >> 1)]       = __floats2half2_rn(v0.x, v0.y);
            Ch[(size_t)(row + 8) * (DD / 2) + (col >> 1)] = __floats2half2_rn(v1.x, v1.y);
            if (z == 0) {
                *(float2*)(g_q + (size_t)row * DD + col) = v0;
                *(float2*)(g_q + (size_t)(row + 8) * DD + col) = v1;
            }
        }
    }
}

// ---- out-projection: C = R + relu(O@Wo + bo), grid (8, 128) ----
__global__ void __launch_bounds__(128, 4) outproj(
    const float* __restrict__ bo, float* __restrict__ C)
{
    const uint32_t sbase = (uint32_t)__cvta_generic_to_shared(gsm);
    const int tid = threadIdx.x, lane = tid & 31, w = tid >> 5;
    const int m0 = blockIdx.y << 6, n0 = blockIdx.x << 6;
    const int wm = (w & 1) << 5, wn = (w >> 1) << 5;

    GemmAcc A;
    gemm_core64(g_oh, g_Wh[3], sbase, m0, n0, wm, wn, tid, lane, A);

#pragma unroll
    for (int mf = 0; mf < 2; mf++) {
        int row = m0 + wm + (mf << 4) + (lane >> 2);
#pragma unroll
        for (int nf = 0; nf < 4; nf++) {
            int col = n0 + wn + (nf << 3) + ((lane & 3) << 1);
            float2 bb = *(const float2*)(bo + col);
            float2 v0 = make_float2(A.a[mf][nf][0] + bb.x, A.a[mf][nf][1] + bb.y);
            float2 v1 = make_float2(A.a[mf][nf][2] + bb.x, A.a[mf][nf][3] + bb.y);
            float2 r0 = *(const float2*)(g_o + (size_t)row * DD + col);
            float2 r1 = *(const float2*)(g_o + (size_t)(row + 8) * DD + col);
            v0.x = r0.x + fmaxf(v0.x, 0.f); v0.y = r0.y + fmaxf(v0.y, 0.f);
            v1.x = r1.x + fmaxf(v1.x, 0.f); v1.y = r1.y + fmaxf(v1.y, 0.f);
            *(float2*)(C + (size_t)row * DD + col) = v0;
            *(float2*)(C + (size_t)(row + 8) * DD + col) = v1;
        }
    }
}

// ======================================================================
// Fused attention v6: R12 structure (4 warps x 16 i-rows, grid (16,64),
// 128 thr, 4 CTAs/SM, separate Qs + double K/V) with:
//  - exp via ex2.approx.f16x2 (h2exp2) on pre-packed half2
//  - Z accumulated by tensor core: extra mma vs all-ones B fragment
// smem: Qs 64x144B | Ks[2] | Vs[2] = 46080 B
// ======================================================================
#define QS_B 0
#define KS_B(bu) (9216 + (bu) * 9216)
#define VS_B(bu) (27648 + (bu) * 9216)
#define FUSED_SMEM_BYTES 46080

extern __shared__ uint32_t smw[];

__global__ void __launch_bounds__(128, 4) fused_attn()
{
    const uint32_t sbase = (uint32_t)__cvta_generic_to_shared(smw);

    const int tid = threadIdx.x, lane = tid & 31, wid = tid >> 5;
    const int hb = blockIdx.y, h = hb >> 3, b = hb & 7;
    const int i0 = blockIdx.x << 6;
    const int r = (wid << 4) + (lane >> 2);

    {
        const __half* src = g_qh + (size_t)(b * NPT + i0) * DD + h * DH;
#pragma unroll
        for (int t = 0; t < 4; t++) {
            int c = tid + (t << 7);
            int rr = c >> 3, seg = c & 7;
            cpa16(sbase + QS_B + rr * 144 + seg * 16,
                  (const char*)(src + (size_t)rr * DD) + seg * 16);
        }
        CP_COMMIT();
    }
    const __half* kbase = g_kh + (size_t)(b * NPT) * DD + h * DH;
    const __half* vbase = g_vh + (size_t)(b * NPT) * DD + h * DH;
#pragma unroll
    for (int t = 0; t < 4; t++) {
        int c = tid + (t << 7);
        int rr = c >> 3, seg = c & 7;
        cpa16(sbase + KS_B(0) + rr * 144 + seg * 16,
              (const char*)(kbase + (size_t)rr * DD) + seg * 16);
        cpa16(sbase + VS_B(0) + rr * 144 + seg * 16,
              (const char*)(vbase + (size_t)rr * DD) + seg * 16);
    }
    CP_COMMIT();

    uint32_t qf[4][4];
    CP_WAIT(1);
    __syncthreads();
    {
        const uint32_t qrow = (uint32_t)((wid << 4) + (lane & 7) + (((lane >> 3) & 1) << 3));
        const uint32_t koff = ((lane >> 4) & 1) << 4;
#pragma unroll
        for (int kc = 0; kc < 4; kc++)
            ldmx4(qf[kc][0], qf[kc][1], qf[kc][2], qf[kc][3],
                  sbase + QS_B + qrow * 144 + koff + kc * 32);
    }

    float oacc[8][4];
#pragma unroll
    for (int nf = 0; nf < 8; nf++)
#pragma unroll
        for (int x = 0; x < 4; x++) oacc[nf][x] = 0.f;
    float zacc[4] = {0.f, 0.f, 0.f, 0.f};
    const uint32_t ONES2 = 0x3C003C00u;   // fp16 (1.0, 1.0)

    __half2* Aout = (__half2*)(g_A + (size_t)hb * NPT * NPT);

    for (int it = 0; it < 16; it++) {
        const int cur = it & 1;
        const uint32_t ksb = sbase + KS_B(cur);
        const uint32_t vsb = sbase + VS_B(cur);
        const int j0 = it << 6;

        CP_WAIT(0);
        __syncthreads();

        if (it + 1 < 16) {
            const int nb = cur ^ 1;
            const __half* kc = kbase + (size_t)(j0 + 64) * DD;
            const __half* vc = vbase + (size_t)(j0 + 64) * DD;
#pragma unroll
            for (int t = 0; t < 4; t++) {
                int c = tid + (t << 7);
                int rr = c >> 3, seg = c & 7;
                cpa16(sbase + KS_B(nb) + rr * 144 + seg * 16,
                      (const char*)(kc + (size_t)rr * DD) + seg * 16);
                cpa16(sbase + VS_B(nb) + rr * 144 + seg * 16,
                      (const char*)(vc + (size_t)rr * DD) + seg * 16);
            }
            CP_COMMIT();
        }

        const uint32_t kboff = (((lane >> 3) & 1) << 4);
#pragma unroll
        for (int ks = 0; ks < 4; ks++) {
            uint32_t pe0, pe1, po0, po1;
#pragma unroll
            for (int t = 0; t < 2; t++) {
                const int nf = (ks << 1) + t;
                float s4[4] = {0.f, 0.f, 0.f, 0.f};
                uint32_t baddr = ksb + (uint32_t)((nf << 3) + (lane & 7)) * 144 + kboff;
#pragma unroll
                for (int kc = 0; kc < 4; kc++) {
                    uint32_t b0, b1;
                    ldmx2(b0, b1, baddr + kc * 32);
                    mma16h(s4, qf[kc][0], qf[kc][1], qf[kc][2], qf[kc][3], b0, b1);
                }
                // exp(s*SCALE) = 2^(s*SCALE*log2e), computed in fp16x2
                __half2 lo = h2exp2(__floats2half2_rn(s4[0] * SCLOG2E, s4[1] * SCLOG2E));
                __half2 hi = h2exp2(__floats2half2_rn(s4[2] * SCLOG2E, s4[3] * SCLOG2E));
                int col = j0 + (nf << 3) + ((lane & 3) << 1);
                Aout[(size_t)(i0 + r) * (NPT >> 1) + (col >> 1)]     = lo;
                Aout[(size_t)(i0 + r + 8) * (NPT >> 1) + (col >> 1)] = hi;
                if (t == 0) { pe0 = *(uint32_t*)&lo; pe1 = *(uint32_t*)&hi; }
                else        { po0 = *(uint32_t*)&lo; po1 = *(uint32_t*)&hi; }
            }
            // Z += P . ones  (tensor-core row sum of the fp16 U)
            mma16h(zacc, pe0, pe1, po0, po1, ONES2, ONES2);
            // O += P . V
            uint32_t rowaddr = vsb + (uint32_t)((ks << 4) + (lane & 15)) * 144;
#pragma unroll
            for (int nf2 = 0; nf2 < 8; nf2++) {
                uint32_t b0, b1;
                ldmx2t(b0, b1, rowaddr + (nf2 << 4));
                mma16h(oacc[nf2], pe0, pe1, po0, po1, b0, b1);
            }
        }
    }

    // zacc[0] = full Z for row r; zacc[2] = full Z for row r+8 (all lanes
    // in a row-group hold identical values because B was all-ones).
    float iz0 = 1.0f / zacc[0], iz1 = 1.0f / zacc[2];
    if ((lane & 3) == 0) {
        g_Z[(size_t)hb * NPT + i0 + r]     = iz0;
        g_Z[(size_t)hb * NPT + i0 + r + 8] = iz1;
    }

    __half2* Oh = (__half2*)g_oh;
#pragma unroll
    for (int nf = 0; nf < 8; nf++) {
        int d = (nf << 3) + ((lane & 3) << 1);
        size_t gi0 = (size_t)(b * NPT + i0 + r) * DD + h * DH + d;
        size_t gi1 = gi0 + (size_t)8 * DD;
        float2 q0 = *(const float2*)(g_q + gi0);
        float2 q1 = *(const float2*)(g_q + gi1);
        float2 o0 = make_float2(q0.x + oacc[nf][0] * iz0, q0.y + oacc[nf][1] * iz0);
        float2 o1 = make_float2(q1.x + oacc[nf][2] * iz1, q1.y + oacc[nf][3] * iz1);
        *(float2*)(g_o + gi0) = o0;
        *(float2*)(g_o + gi1) = o1;
        Oh[gi0 >> 1] = __floats2half2_rn(o0.x, o0.y);
        Oh[gi1 >> 1] = __floats2half2_rn(o1.x, o1.y);
    }
}

// ======================================================================
// Am[b, j, i] = (1/8) * sum_h U[h,b,i,j] * invZ[h,b,i]   (half2 reads)
// ======================================================================
__global__ void __launch_bounds__(256) meanA_kernel(float* __restrict__ out)
{
    __shared__ float s[64][33];
    __shared__ float ziv[8][32];
    const int b  = blockIdx.z;
    const int i0 = blockIdx.x << 5;
    const int j0 = blockIdx.y << 6;
    const int tx = threadIdx.x & 31;
    const int ty = threadIdx.x >> 5;

    ziv[ty][tx] = g_Z[(size_t)(ty * NB + b) * NPT + i0 + tx];
    __syncthreads();

    float2 acc[4];
#pragma unroll
    for (int r = 0; r < 4; r++) acc[r] = make_float2(0.f, 0.f);

#pragma unroll
    for (int h = 0; h < 8; h++) {
        const __half2* base = (const __half2*)(
            g_A + ((size_t)(h * NB + b) * NPT + i0) * NPT + j0);
#pragma unroll
        for (int r = 0; r < 4; r++) {
            int ii = ty + (r << 3);
            float2 f = __half22float2(base[(size_t)ii * (NPT >> 1) + tx]);
            float z = ziv[h][ii];
            acc[r].x += f.x * z;
            acc[r].y += f.y * z;
        }
    }
#pragma unroll
    for (int r = 0; r < 4; r++) {
        int ii = ty + (r << 3);
        s[2 * tx][ii]     = acc[r].x * 0.125f;
        s[2 * tx + 1][ii] = acc[r].y * 0.125f;
    }
    __syncthreads();

    float* ob = out + ((size_t)b * NPT + j0) * NPT + i0;
#pragma unroll
    for (int rr = 0; rr < 8; rr++) {
        int jj = ty + (rr << 3);
        ob[(size_t)jj * NPT + tx] = s[jj][tx];
    }
}

// ======================================================================
// Launch — meanA forked onto a side stream, overlapping outproj.
// ======================================================================
extern "C" void kernel_launch(void* const* d_in, const int* in_sizes, int n_in,
                              void* d_out, int out_size)
{
    const float* Q  = (const float*)d_in[0];
    const float* K  = (const float*)d_in[1];
    const float* Wq = (const float*)d_in[2];
    const float* bq = (const float*)d_in[3];
    const float* Wk = (const float*)d_in[4];
    const float* bk = (const float*)d_in[5];
    const float* Wv = (const float*)d_in[6];
    const float* bv = (const float*)d_in[7];
    const float* Wo = (const float*)d_in[8];
    const float* bo = (const float*)d_in[9];
    float* out = (float*)d_out;

    static bool init = false;
    static cudaStream_t s2;
    static cudaEvent_t evFork, evJoin;
    if (!init) {
        cudaFuncSetAttribute(fused_attn, cudaFuncAttributeMaxDynamicSharedMemorySize,
                             FUSED_SMEM_BYTES);
        cudaFuncSetAttribute(proj3, cudaFuncAttributeMaxDynamicSharedMemorySize,
                             GEMM_SMEM_BYTES);
        cudaFuncSetAttribute(outproj, cudaFuncAttributeMaxDynamicSharedMemorySize,
                             GEMM_SMEM_BYTES);
        cudaStreamCreateWithFlags(&s2, cudaStreamNonBlocking);
        cudaEventCreateWithFlags(&evFork, cudaEventDisableTiming);
        cudaEventCreateWithFlags(&evJoin, cudaEventDisableTiming);
        init = true;
    }

    cvt_all<<<dim3(1024, 6), 256>>>(Q, K, Wq, Wk, Wv, Wo);

    proj3<<<dim3(8, 128, 3), 128, GEMM_SMEM_BYTES>>>(bq, bk, bv);

    fused_attn<<<dim3(16, 64), 128, FUSED_SMEM_BYTES>>>();

    // fork: meanA (reads g_A, g_Z) runs concurrently with outproj (reads g_oh, g_o)
    cudaEventRecord(evFork, 0);
    cudaStreamWaitEvent(s2, evFork, 0);
    meanA_kernel<<<dim3(32, 16, 8), 256, 0, s2>>>(out + (size_t)MM * DD);

    outproj<<<dim3(8, 128), 128, GEMM_SMEM_BYTES>>>(bo, out);

    // join
    cudaEventRecord(evJoin, s2);
    cudaStreamWaitEvent(0, evJoin, 0);
}

// round 16
// speedup vs baseline: 1.1217x; 1.0441x over previous
#include <cuda_runtime.h>
#include <cuda_fp16.h>
#include <cstdint>

#define NB  8
#define NPT 1024
#define DD  512
#define NH  8
#define DH  64
#define MM  (NB * NPT)
#define SCALE 0.04419417382415922f                 // 1/sqrt(512)
#define SCLOG2E (0.04419417382415922f * 1.4426950408889634f)

// ---------------- scratch (device globals; allocation-free) ----------------
__device__ __half g_qh [(size_t)MM * DD];            // fp16 q (also residual)
__device__ __half g_kh [(size_t)MM * DD];            // fp16 k
__device__ __half g_vh [(size_t)MM * DD];            // fp16 v
__device__ float  g_o  [(size_t)MM * DD];            // fp32 O (residual for out-proj)
__device__ __half g_oh [(size_t)MM * DD];            // fp16 O (mma operand)
__device__ __half g_Qin[(size_t)MM * DD];            // fp16 raw Q
__device__ __half g_Kin[(size_t)MM * DD];            // fp16 raw K
__device__ __half g_Wh [4][(size_t)DD * DD];         // fp16 Wq,Wk,Wv,Wo
__device__ __half g_A  [(size_t)NH * NB * NPT * NPT];// U = exp(s), fp16
__device__ float  g_Z  [(size_t)NH * NB * NPT];      // 1/rowsum

// ---------------- helpers ----------------
__device__ __forceinline__ void mma16h(float* c, uint32_t a0, uint32_t a1,
                                       uint32_t a2, uint32_t a3,
                                       uint32_t b0, uint32_t b1) {
    asm volatile(
        "mma.sync.aligned.m16n8k16.row.col.f32.f16.f16.f32 "
        "{%0,%1,%2,%3},{%4,%5,%6,%7},{%8,%9},{%0,%1,%2,%3};"
        : "+f"(c[0]), "+f"(c[1]), "+f"(c[2]), "+f"(c[3])
        : "r"(a0), "r"(a1), "r"(a2), "r"(a3), "r"(b0), "r"(b1));
}
__device__ __forceinline__ void ldmx4(uint32_t& a0, uint32_t& a1, uint32_t& a2,
                                      uint32_t& a3, uint32_t addr) {
    asm volatile("ldmatrix.sync.aligned.m8n8.x4.shared.b16 {%0,%1,%2,%3}, [%4];"
                 : "=r"(a0), "=r"(a1), "=r"(a2), "=r"(a3) : "r"(addr));
}
__device__ __forceinline__ void ldmx2(uint32_t& b0, uint32_t& b1, uint32_t addr) {
    asm volatile("ldmatrix.sync.aligned.m8n8.x2.shared.b16 {%0,%1}, [%2];"
                 : "=r"(b0), "=r"(b1) : "r"(addr));
}
__device__ __forceinline__ void ldmx2t(uint32_t& b0, uint32_t& b1, uint32_t addr) {
    asm volatile("ldmatrix.sync.aligned.m8n8.x2.trans.shared.b16 {%0,%1}, [%2];"
                 : "=r"(b0), "=r"(b1) : "r"(addr));
}
__device__ __forceinline__ void cpa16(uint32_t dst, const void* src) {
    asm volatile("cp.async.cg.shared.global [%0], [%1], 16;" :: "r"(dst), "l"(src));
}
#define CP_COMMIT() asm volatile("cp.async.commit_group;")
#define CP_WAIT(N)  asm volatile("cp.async.wait_group %0;" :: "n"(N))

// ======================================================================
// fp32 -> fp16 conversion, single launch.
// ======================================================================
__global__ void __launch_bounds__(256) cvt_all(
    const float* __restrict__ Q, const float* __restrict__ K,
    const float* __restrict__ W0, const float* __restrict__ W1,
    const float* __restrict__ W2, const float* __restrict__ W3)
{
    const int job = blockIdx.y;
    if (job >= 2) {
        if (blockIdx.x >= 64) return;
        const float* ws[4] = {W0, W1, W2, W3};
        const float4* src = (const float4*)ws[job - 2];
        __half2* dst = (__half2*)g_Wh[job - 2];
        int i = blockIdx.x * 256 + threadIdx.x;
#pragma unroll
        for (int t = 0; t < 4; t++) {
            int idx = i + t * (64 * 256);
            float4 v = src[idx];
            dst[2 * idx]     = __floats2half2_rn(v.x, v.y);
            dst[2 * idx + 1] = __floats2half2_rn(v.z, v.w);
        }
        return;
    }
    const float4* src = (const float4*)(job ? K : Q);
    __half2* dst = (__half2*)(job ? g_Kin : g_Qin);
    int i = blockIdx.x * 256 + threadIdx.x;
#pragma unroll
    for (int t = 0; t < 4; t++) {
        int idx = i + t * (1024 * 256);
        float4 v = src[idx];
        dst[2 * idx]     = __floats2half2_rn(v.x, v.y);
        dst[2 * idx + 1] = __floats2half2_rn(v.z, v.w);
    }
}

// ======================================================================
// GEMM core 64x64, 3-stage cp.async pipeline, K-chunk 64. (R12, proven)
// smem bytes: Xs[3] 64x144B | Ws[3] 64x144B = 55296
// ======================================================================
#define GX_B(bu) ((bu) * 9216)
#define GW_B(bu) (27648 + (bu) * 9216)
#define GEMM_SMEM_BYTES 55296

struct GemmAcc { float a[2][4][4]; };

__device__ __forceinline__ void gemm_stage_load(
    const __half* __restrict__ Xh, const __half* __restrict__ Wh,
    uint32_t sbase, int m0, int n0, int tid, int stage, int k0)
{
#pragma unroll
    for (int t = 0; t < 4; t++) {
        int c = tid + (t << 7);
        int rr = c >> 3, seg = c & 7;
        cpa16(sbase + GX_B(stage) + rr * 144 + seg * 16,
              (const char*)(Xh + (size_t)(m0 + rr) * DD + k0) + seg * 16);
        cpa16(sbase + GW_B(stage) + rr * 144 + seg * 16,
              (const char*)(Wh + (size_t)(k0 + rr) * DD + n0) + seg * 16);
    }
    CP_COMMIT();
}

__device__ __forceinline__ void gemm_core64(
    const __half* __restrict__ Xh, const __half* __restrict__ Wh,
    uint32_t sbase, int m0, int n0, int wm, int wn,
    int tid, int lane, GemmAcc& A)
{
#pragma unroll
    for (int mf = 0; mf < 2; mf++)
#pragma unroll
        for (int nf = 0; nf < 4; nf++)
#pragma unroll
            for (int x = 0; x < 4; x++) A.a[mf][nf][x] = 0.f;

    gemm_stage_load(Xh, Wh, sbase, m0, n0, tid, 0, 0);
    gemm_stage_load(Xh, Wh, sbase, m0, n0, tid, 1, 64);

    const uint32_t arow = (uint32_t)((lane & 7) + (((lane >> 3) & 1) << 3));
    const uint32_t akoff = ((lane >> 4) & 1) << 4;
    const uint32_t brow = (uint32_t)(lane & 15);

    int buf = 0;
    for (int kc64 = 0; kc64 < 8; kc64++) {
        if (kc64 < 7) { CP_WAIT(1); } else { CP_WAIT(0); }
        __syncthreads();

        const uint32_t xsb = sbase + GX_B(buf);
        const uint32_t wsb = sbase + GW_B(buf);

        if (kc64 + 2 < 8) {
            int nb = buf + 2; if (nb >= 3) nb -= 3;
            gemm_stage_load(Xh, Wh, sbase, m0, n0, tid, nb, (kc64 + 2) << 6);
        }

#pragma unroll
        for (int kc = 0; kc < 4; kc++) {
            uint32_t af[2][4];
#pragma unroll
            for (int mf = 0; mf < 2; mf++)
                ldmx4(af[mf][0], af[mf][1], af[mf][2], af[mf][3],
                      xsb + (uint32_t)(wm + (mf << 4) + arow) * 144 + akoff + kc * 32);
#pragma unroll
            for (int nf = 0; nf < 4; nf++) {
                uint32_t b0, b1;
                ldmx2t(b0, b1, wsb + ((kc << 4) + brow) * 144 + wn * 2 + (nf << 4));
#pragma unroll
                for (int mf = 0; mf < 2; mf++)
                    mma16h(A.a[mf][nf], af[mf][0], af[mf][1], af[mf][2], af[mf][3], b0, b1);
            }
        }
        if (++buf >= 3) buf = 0;
    }
}

extern __shared__ uint32_t gsm[];

// ---- merged projection GEMM: grid (8, 128, 3); z: 0=q, 1=k, 2=v ----
__global__ void __launch_bounds__(128, 4) proj3(
    const float* __restrict__ bq, const float* __restrict__ bk,
    const float* __restrict__ bv)
{
    const uint32_t sbase = (uint32_t)__cvta_generic_to_shared(gsm);
    const int tid = threadIdx.x, lane = tid & 31, w = tid >> 5;
    const int m0 = blockIdx.y << 6, n0 = blockIdx.x << 6;
    const int wm = (w & 1) << 5, wn = (w >> 1) << 5;
    const int z = blockIdx.z;

    const __half* Xh = (z == 0) ? g_Qin : g_Kin;
    const __half* Wh = g_Wh[z];
    const float* bias = (z == 0) ? bq : (z == 1) ? bk : bv;

    GemmAcc A;
    gemm_core64(Xh, Wh, sbase, m0, n0, wm, wn, tid, lane, A);

    __half2* Ch = (__half2*)((z == 0) ? g_qh : (z == 1) ? g_kh : g_vh);
#pragma unroll
    for (int mf = 0; mf < 2; mf++) {
        int row = m0 + wm + (mf << 4) + (lane >> 2);
#pragma unroll
        for (int nf = 0; nf < 4; nf++) {
            int col = n0 + wn + (nf << 3) + ((lane & 3) << 1);
            float2 bb = *(const float2*)(bias + col);
            float2 v0 = make_float2(A.a[mf][nf][0] + bb.x, A.a[mf][nf][1] + bb.y);
            float2 v1 = make_float2(A.a[mf][nf][2] + bb.x, A.a[mf][nf][3] + bb.y);
            Ch[(size_t)row * (DD / 2) + (col >> 1)]       = __floats2half2_rn(v0.x, v0.y);
            Ch[(size_t)(row + 8) * (DD / 2) + (col >> 1)] = __floats2half2_rn(v1.x, v1.y);
        }
    }
}

// ---- out-projection: C = R + relu(O@Wo + bo), grid (8, 128) ----
__global__ void __launch_bounds__(128, 4) outproj(
    const float* __restrict__ bo, float* __restrict__ C)
{
    const uint32_t sbase = (uint32_t)__cvta_generic_to_shared(gsm);
    const int tid = threadIdx.x, lane = tid & 31, w = tid >> 5;
    const int m0 = blockIdx.y << 6, n0 = blockIdx.x << 6;
    const int wm = (w & 1) << 5, wn = (w >> 1) << 5;

    GemmAcc A;
    gemm_core64(g_oh, g_Wh[3], sbase, m0, n0, wm, wn, tid, lane, A);

#pragma unroll
    for (int mf = 0; mf < 2; mf++) {
        int row = m0 + wm + (mf << 4) + (lane >> 2);
#pragma unroll
        for (int nf = 0; nf < 4; nf++) {
            int col = n0 + wn + (nf << 3) + ((lane & 3) << 1);
            float2 bb = *(const float2*)(bo + col);
            float2 v0 = make_float2(A.a[mf][nf][0] + bb.x, A.a[mf][nf][1] + bb.y);
            float2 v1 = make_float2(A.a[mf][nf][2] + bb.x, A.a[mf][nf][3] + bb.y);
            float2 r0 = *(const float2*)(g_o + (size_t)row * DD + col);
            float2 r1 = *(const float2*)(g_o + (size_t)(row + 8) * DD + col);
            v0.x = r0.x + fmaxf(v0.x, 0.f); v0.y = r0.y + fmaxf(v0.y, 0.f);
            v1.x = r1.x + fmaxf(v1.x, 0.f); v1.y = r1.y + fmaxf(v1.y, 0.f);
            *(float2*)(C + (size_t)row * DD + col) = v0;
            *(float2*)(C + (size_t)(row + 8) * DD + col) = v1;
        }
    }
}

// ======================================================================
// Fused attention v7: R14 (h2exp2 + Z-mma) + residual from smem Qs.
// 4 warps x 16 i-rows, grid (16, 64), 128 thr, 4 CTAs/SM.
// smem: Qs 64x144B | Ks[2] | Vs[2] = 46080 B
// ======================================================================
#define QS_B 0
#define KS_B(bu) (9216 + (bu) * 9216)
#define VS_B(bu) (27648 + (bu) * 9216)
#define FUSED_SMEM_BYTES 46080

extern __shared__ uint32_t smw[];

__global__ void __launch_bounds__(128, 4) fused_attn()
{
    const uint32_t sbase = (uint32_t)__cvta_generic_to_shared(smw);

    const int tid = threadIdx.x, lane = tid & 31, wid = tid >> 5;
    const int hb = blockIdx.y, h = hb >> 3, b = hb & 7;
    const int i0 = blockIdx.x << 6;
    const int r = (wid << 4) + (lane >> 2);

    {
        const __half* src = g_qh + (size_t)(b * NPT + i0) * DD + h * DH;
#pragma unroll
        for (int t = 0; t < 4; t++) {
            int c = tid + (t << 7);
            int rr = c >> 3, seg = c & 7;
            cpa16(sbase + QS_B + rr * 144 + seg * 16,
                  (const char*)(src + (size_t)rr * DD) + seg * 16);
        }
        CP_COMMIT();
    }
    const __half* kbase = g_kh + (size_t)(b * NPT) * DD + h * DH;
    const __half* vbase = g_vh + (size_t)(b * NPT) * DD + h * DH;
#pragma unroll
    for (int t = 0; t < 4; t++) {
        int c = tid + (t << 7);
        int rr = c >> 3, seg = c & 7;
        cpa16(sbase + KS_B(0) + rr * 144 + seg * 16,
              (const char*)(kbase + (size_t)rr * DD) + seg * 16);
        cpa16(sbase + VS_B(0) + rr * 144 + seg * 16,
              (const char*)(vbase + (size_t)rr * DD) + seg * 16);
    }
    CP_COMMIT();

    uint32_t qf[4][4];
    CP_WAIT(1);
    __syncthreads();
    {
        const uint32_t qrow = (uint32_t)((wid << 4) + (lane & 7) + (((lane >> 3) & 1) << 3));
        const uint32_t koff = ((lane >> 4) & 1) << 4;
#pragma unroll
        for (int kc = 0; kc < 4; kc++)
            ldmx4(qf[kc][0], qf[kc][1], qf[kc][2], qf[kc][3],
                  sbase + QS_B + qrow * 144 + koff + kc * 32);
    }

    float oacc[8][4];
#pragma unroll
    for (int nf = 0; nf < 8; nf++)
#pragma unroll
        for (int x = 0; x < 4; x++) oacc[nf][x] = 0.f;
    float zacc[4] = {0.f, 0.f, 0.f, 0.f};
    const uint32_t ONES2 = 0x3C003C00u;   // fp16 (1.0, 1.0)

    __half2* Aout = (__half2*)(g_A + (size_t)hb * NPT * NPT);

    for (int it = 0; it < 16; it++) {
        const int cur = it & 1;
        const uint32_t ksb = sbase + KS_B(cur);
        const uint32_t vsb = sbase + VS_B(cur);
        const int j0 = it << 6;

        CP_WAIT(0);
        __syncthreads();

        if (it + 1 < 16) {
            const int nb = cur ^ 1;
            const __half* kc = kbase + (size_t)(j0 + 64) * DD;
            const __half* vc = vbase + (size_t)(j0 + 64) * DD;
#pragma unroll
            for (int t = 0; t < 4; t++) {
                int c = tid + (t << 7);
                int rr = c >> 3, seg = c & 7;
                cpa16(sbase + KS_B(nb) + rr * 144 + seg * 16,
                      (const char*)(kc + (size_t)rr * DD) + seg * 16);
                cpa16(sbase + VS_B(nb) + rr * 144 + seg * 16,
                      (const char*)(vc + (size_t)rr * DD) + seg * 16);
            }
            CP_COMMIT();
        }

        const uint32_t kboff = (((lane >> 3) & 1) << 4);
#pragma unroll
        for (int ks = 0; ks < 4; ks++) {
            uint32_t pe0, pe1, po0, po1;
#pragma unroll
            for (int t = 0; t < 2; t++) {
                const int nf = (ks << 1) + t;
                float s4[4] = {0.f, 0.f, 0.f, 0.f};
                uint32_t baddr = ksb + (uint32_t)((nf << 3) + (lane & 7)) * 144 + kboff;
#pragma unroll
                for (int kc = 0; kc < 4; kc++) {
                    uint32_t b0, b1;
                    ldmx2(b0, b1, baddr + kc * 32);
                    mma16h(s4, qf[kc][0], qf[kc][1], qf[kc][2], qf[kc][3], b0, b1);
                }
                __half2 lo = h2exp2(__floats2half2_rn(s4[0] * SCLOG2E, s4[1] * SCLOG2E));
                __half2 hi = h2exp2(__floats2half2_rn(s4[2] * SCLOG2E, s4[3] * SCLOG2E));
                int col = j0 + (nf << 3) + ((lane & 3) << 1);
                Aout[(size_t)(i0 + r) * (NPT >> 1) + (col >> 1)]     = lo;
                Aout[(size_t)(i0 + r + 8) * (NPT >> 1) + (col >> 1)] = hi;
                if (t == 0) { pe0 = *(uint32_t*)&lo; pe1 = *(uint32_t*)&hi; }
                else        { po0 = *(uint32_t*)&lo; po1 = *(uint32_t*)&hi; }
            }
            mma16h(zacc, pe0, pe1, po0, po1, ONES2, ONES2);
            uint32_t rowaddr = vsb + (uint32_t)((ks << 4) + (lane & 15)) * 144;
#pragma unroll
            for (int nf2 = 0; nf2 < 8; nf2++) {
                uint32_t b0, b1;
                ldmx2t(b0, b1, rowaddr + (nf2 << 4));
                mma16h(oacc[nf2], pe0, pe1, po0, po1, b0, b1);
            }
        }
    }

    float iz0 = 1.0f / zacc[0], iz1 = 1.0f / zacc[2];
    if ((lane & 3) == 0) {
        g_Z[(size_t)hb * NPT + i0 + r]     = iz0;
        g_Z[(size_t)hb * NPT + i0 + r + 8] = iz1;
    }

    // ---- epilogue: residual = fp16 q read back from smem Qs (free) ----
    __half2* Oh = (__half2*)g_oh;
#pragma unroll
    for (int nf = 0; nf < 8; nf++) {
        int d = (nf << 3) + ((lane & 3) << 1);
        // Qs word index: row*36 + d/2 (144B rows = 36 words)
        __half2 qh0 = *(__half2*)&smw[(QS_B >> 2) + r * 36 + (d >> 1)];
        __half2 qh1 = *(__half2*)&smw[(QS_B >> 2) + (r + 8) * 36 + (d >> 1)];
        float2 q0 = __half22float2(qh0);
        float2 q1 = __half22float2(qh1);
        size_t gi0 = (size_t)(b * NPT + i0 + r) * DD + h * DH + d;
        size_t gi1 = gi0 + (size_t)8 * DD;
        float2 o0 = make_float2(q0.x + oacc[nf][0] * iz0, q0.y + oacc[nf][1] * iz0);
        float2 o1 = make_float2(q1.x + oacc[nf][2] * iz1, q1.y + oacc[nf][3] * iz1);
        *(float2*)(g_o + gi0) = o0;
        *(float2*)(g_o + gi1) = o1;
        Oh[gi0 >> 1] = __floats2half2_rn(o0.x, o0.y);
        Oh[gi1 >> 1] = __floats2half2_rn(o1.x, o1.y);
    }
}

// ======================================================================
// Am[b, j, i] = (1/8) * sum_h U[h,b,i,j] * invZ[h,b,i]
// v2: j-tile 128, uint2 (8B) loads. grid (32 i, 8 j, 8 b), 256 thr.
// ======================================================================
__global__ void __launch_bounds__(256) meanA_kernel(float* __restrict__ out)
{
    __shared__ float s[128][33];
    __shared__ float ziv[8][32];
    const int b  = blockIdx.z;
    const int i0 = blockIdx.x << 5;
    const int j0 = blockIdx.y << 7;
    const int tx = threadIdx.x & 31;
    const int ty = threadIdx.x >> 5;   // 0..7

    ziv[ty][tx] = g_Z[(size_t)(ty * NB + b) * NPT + i0 + tx];
    __syncthreads();

    float4 acc[4];
#pragma unroll
    for (int r = 0; r < 4; r++) acc[r] = make_float4(0.f, 0.f, 0.f, 0.f);

#pragma unroll
    for (int h = 0; h < 8; h++) {
        const uint2* base = (const uint2*)(
            g_A + ((size_t)(h * NB + b) * NPT + i0) * NPT + j0);
#pragma unroll
        for (int r = 0; r < 4; r++) {
            int ii = ty + (r << 3);
            uint2 v = base[(size_t)ii * (NPT >> 2) + tx];
            float2 f0 = __half22float2(*(__half2*)&v.x);
            float2 f1 = __half22float2(*(__half2*)&v.y);
            float z = ziv[h][ii];
            acc[r].x += f0.x * z; acc[r].y += f0.y * z;
            acc[r].z += f1.x * z; acc[r].w += f1.y * z;
        }
    }
#pragma unroll
    for (int r = 0; r < 4; r++) {
        int ii = ty + (r << 3);
        s[4 * tx + 0][ii] = acc[r].x * 0.125f;
        s[4 * tx + 1][ii] = acc[r].y * 0.125f;
        s[4 * tx + 2][ii] = acc[r].z * 0.125f;
        s[4 * tx + 3][ii] = acc[r].w * 0.125f;
    }
    __syncthreads();

    float* ob = out + ((size_t)b * NPT + j0) * NPT + i0;
#pragma unroll
    for (int rr = 0; rr < 16; rr++) {
        int jj = ty + (rr << 3);
        ob[(size_t)jj * NPT + tx] = s[jj][tx];
    }
}

// ======================================================================
// Launch — meanA forked onto a side stream, overlapping outproj.
// ======================================================================
extern "C" void kernel_launch(void* const* d_in, const int* in_sizes, int n_in,
                              void* d_out, int out_size)
{
    const float* Q  = (const float*)d_in[0];
    const float* K  = (const float*)d_in[1];
    const float* Wq = (const float*)d_in[2];
    const float* bq = (const float*)d_in[3];
    const float* Wk = (const float*)d_in[4];
    const float* bk = (const float*)d_in[5];
    const float* Wv = (const float*)d_in[6];
    const float* bv = (const float*)d_in[7];
    const float* Wo = (const float*)d_in[8];
    const float* bo = (const float*)d_in[9];
    float* out = (float*)d_out;

    static bool init = false;
    static cudaStream_t s2;
    static cudaEvent_t evFork, evJoin;
    if (!init) {
        cudaFuncSetAttribute(fused_attn, cudaFuncAttributeMaxDynamicSharedMemorySize,
                             FUSED_SMEM_BYTES);
        cudaFuncSetAttribute(proj3, cudaFuncAttributeMaxDynamicSharedMemorySize,
                             GEMM_SMEM_BYTES);
        cudaFuncSetAttribute(outproj, cudaFuncAttributeMaxDynamicSharedMemorySize,
                             GEMM_SMEM_BYTES);
        cudaStreamCreateWithFlags(&s2, cudaStreamNonBlocking);
        cudaEventCreateWithFlags(&evFork, cudaEventDisableTiming);
        cudaEventCreateWithFlags(&evJoin, cudaEventDisableTiming);
        init = true;
    }

    cvt_all<<<dim3(1024, 6), 256>>>(Q, K, Wq, Wk, Wv, Wo);

    proj3<<<dim3(8, 128, 3), 128, GEMM_SMEM_BYTES>>>(bq, bk, bv);

    fused_attn<<<dim3(16, 64), 128, FUSED_SMEM_BYTES>>>();

    // fork: meanA (reads g_A, g_Z) runs concurrently with outproj (reads g_oh, g_o)
    cudaEventRecord(evFork, 0);
    cudaStreamWaitEvent(s2, evFork, 0);
    meanA_kernel<<<dim3(32, 8, 8), 256, 0, s2>>>(out + (size_t)MM * DD);

    outproj<<<dim3(8, 128), 128, GEMM_SMEM_BYTES>>>(bo, out);

    // join
    cudaEventRecord(evJoin, s2);
    cudaStreamWaitEvent(0, evJoin, 0);
}